// round 3
// baseline (speedup 1.0000x reference)
#include <cuda_runtime.h>
#include <math.h>
#include <stdint.h>

static constexpr int B_ = 4, S_ = 1024, DM_ = 1024, H_ = 16, DK_ = 64, DV_ = 64;

// Scratch (device globals: no allocation allowed)
__device__ float g_Q[B_*H_*S_*DK_];     // [b,h,s,dk]
__device__ float g_K[B_*H_*S_*DK_];
__device__ float g_V[B_*H_*S_*DV_];
__device__ float g_X[B_*S_*H_*DV_];     // attn out, concat heads: [b,s,h*dv]

__device__ __forceinline__ uint32_t f2tf(float x) {
    uint32_t r;
    asm("cvt.rna.tf32.f32 %0, %1;" : "=r"(r) : "f"(x));
    return r;
}

// D += A * B  (m16n8k8, tf32 inputs, f32 accumulate)
__device__ __forceinline__ void mma8(float* c, const uint32_t* a, const uint32_t* b) {
    asm volatile(
        "mma.sync.aligned.m16n8k8.row.col.f32.tf32.tf32.f32 "
        "{%0,%1,%2,%3}, {%4,%5,%6,%7}, {%8,%9}, {%0,%1,%2,%3};"
        : "+f"(c[0]), "+f"(c[1]), "+f"(c[2]), "+f"(c[3])
        : "r"(a[0]), "r"(a[1]), "r"(a[2]), "r"(a[3]), "r"(b[0]), "r"(b[1]));
}

// ---------------------------------------------------------------------------
// Kernel 1: fused QKV projections. Block tile 128(M) x 64(N), K-chunk 32.
// 256 threads = 8 warps (4m x 2n). Fragment-major smem, single-sync pipeline.
// ---------------------------------------------------------------------------
__global__ __launch_bounds__(256) void qkv_proj_mma(
    const float* __restrict__ q, const float* __restrict__ k, const float* __restrict__ v,
    const float* __restrict__ Wq, const float* __restrict__ Wk, const float* __restrict__ Wv)
{
    const float* x; const float* W; float* out;
    if (blockIdx.z == 0)      { x = q; W = Wq; out = g_Q; }
    else if (blockIdx.z == 1) { x = k; W = Wk; out = g_K; }
    else                      { x = v; W = Wv; out = g_V; }

    const int m0 = blockIdx.x * 128;
    const int h  = blockIdx.y;
    const float* Wh = W + (size_t)h * DM_ * DK_;

    // Fragment-major: Asf[buf][mtg][ks][lane][reg], Bsf[buf][ks][nb][lane][reg]
    __shared__ uint32_t Asf[2][8][4][32][4];   // 32 KB
    __shared__ uint32_t Bsf[2][4][8][32][2];   // 16 KB

    const int tid = threadIdx.x, lane = tid & 31, warp = tid >> 5;
    const int wm = warp & 3, wn = warp >> 2;

    float acc[2][4][4];
    #pragma unroll
    for (int mt = 0; mt < 2; mt++)
        #pragma unroll
        for (int nt = 0; nt < 4; nt++)
            #pragma unroll
            for (int i = 0; i < 4; i++) acc[mt][nt][i] = 0.f;

    float4 aR[4], bR[2];

    auto loadG = [&](int k0) {
        #pragma unroll
        for (int t = 0; t < 4; t++) {
            int idx = tid + t * 256, r = idx >> 3, c = (idx & 7) * 4;
            aR[t] = *(const float4*)&x[(size_t)(m0 + r) * DM_ + k0 + c];
        }
        #pragma unroll
        for (int t = 0; t < 2; t++) {
            int idx = tid + t * 256, r = idx >> 4, c = (idx & 15) * 4;
            bR[t] = *(const float4*)&Wh[(size_t)(k0 + r) * DK_ + c];
        }
    };

    loadG(0);

    for (int it = 0; it < DM_ / 32; it++) {
        const int buf = it & 1;
        // ---- stage current chunk into fragment-major smem ----
        #pragma unroll
        for (int t = 0; t < 4; t++) {
            int idx = tid + t * 256, r = idx >> 3, c0 = (idx & 7) * 4;
            int mtg = r >> 4, rin = r & 15, gg = rin & 7, mh = rin >> 3;
            int ks = c0 >> 3, hh = (c0 >> 2) & 1;
            uint32_t* p = &Asf[buf][mtg][ks][4 * gg][mh + 2 * hh];
            p[0]  = f2tf(aR[t].x); p[4]  = f2tf(aR[t].y);
            p[8]  = f2tf(aR[t].z); p[12] = f2tf(aR[t].w);
        }
        #pragma unroll
        for (int t = 0; t < 2; t++) {
            int idx = tid + t * 256, r = idx >> 4, c0 = (idx & 15) * 4;
            int ks = r >> 3, rem = r & 7, tg = rem & 3, hh = rem >> 2;
            int nb = c0 >> 3, gg = c0 & 7;
            uint32_t* p = &Bsf[buf][ks][nb][4 * gg + tg][hh];
            p[0]  = f2tf(bR[t].x); p[8]  = f2tf(bR[t].y);
            p[16] = f2tf(bR[t].z); p[24] = f2tf(bR[t].w);
        }
        __syncthreads();
        if (it + 1 < DM_ / 32) loadG((it + 1) * 32);

        // ---- compute from smem[buf] ----
        #pragma unroll
        for (int ks = 0; ks < 4; ks++) {
            uint4 afA = *(const uint4*)&Asf[buf][wm * 2 + 0][ks][lane][0];
            uint4 afB = *(const uint4*)&Asf[buf][wm * 2 + 1][ks][lane][0];
            #pragma unroll
            for (int nt = 0; nt < 4; nt++) {
                uint2 bf = *(const uint2*)&Bsf[buf][ks][wn * 4 + nt][lane][0];
                mma8(acc[0][nt], (const uint32_t*)&afA, (const uint32_t*)&bf);
                mma8(acc[1][nt], (const uint32_t*)&afB, (const uint32_t*)&bf);
            }
        }
    }

    const int g = lane >> 2, tig = lane & 3;
    #pragma unroll
    for (int mt = 0; mt < 2; mt++) {
        #pragma unroll
        for (int half = 0; half < 2; half++) {
            int m = m0 + wm * 32 + mt * 16 + g + half * 8;
            int b = m >> 10, s = m & 1023;
            float* op = &out[(((size_t)b * H_ + h) * S_ + s) * DK_];
            #pragma unroll
            for (int nt = 0; nt < 4; nt++) {
                int nn = wn * 32 + nt * 8 + 2 * tig;
                float2 val = half ? make_float2(acc[mt][nt][2], acc[mt][nt][3])
                                  : make_float2(acc[mt][nt][0], acc[mt][nt][1]);
                *(float2*)&op[nn] = val;
            }
        }
    }
}

// ---------------------------------------------------------------------------
// Kernel 2: causal flash attention. 256 threads = 8 warps, 128-row query tile,
// 64-key tiles. Q fragments hoisted to registers; K/V fragment-major smem.
// ---------------------------------------------------------------------------
__global__ __launch_bounds__(256) void attn_mma()
{
    extern __shared__ uint32_t sm[];
    // region layout (words):
    //  [0, 8704)      : union { Qsf[8][8][32][4] (8192) , Ps[128][68] (8704) }
    //  [8704, 12800)  : Ksf[8][8][32][2]
    //  [12800, 16896) : Vsf[8][8][32][2]
    uint32_t (*Qsf)[8][32][4] = (uint32_t(*)[8][32][4])sm;
    uint32_t (*Ps)[68]        = (uint32_t(*)[68])sm;
    uint32_t (*Ksf)[8][32][2] = (uint32_t(*)[8][32][2])(sm + 8704);
    uint32_t (*Vsf)[8][32][2] = (uint32_t(*)[8][32][2])(sm + 12800);

    const int qt = 7 - blockIdx.x;          // descending work for tail balance
    const int bh = blockIdx.y;
    const int b = bh >> 4, h = bh & 15;
    const int tid = threadIdx.x, lane = tid & 31, warp = tid >> 5;
    const int g = lane >> 2, tig = lane & 3;

    const float* Qg = g_Q + (size_t)bh * S_ * DK_ + (size_t)qt * 128 * DK_;
    const float* Kg = g_K + (size_t)bh * S_ * DK_;
    const float* Vg = g_V + (size_t)bh * S_ * DK_;

    // ---- stage Q tile (scaled) into fragment-major layout ----
    #pragma unroll
    for (int t = 0; t < 8; t++) {
        int idx = tid + t * 256, r = idx >> 4, c0 = (idx & 15) * 4;
        int w = r >> 4, rin = r & 15, gq = rin & 7, mh = rin >> 3;
        int ks = c0 >> 3, hh = (c0 >> 2) & 1;
        float4 qv = *(const float4*)&Qg[r * DK_ + c0];
        uint32_t* p = &Qsf[w][ks][4 * gq][mh + 2 * hh];
        p[0]  = f2tf(qv.x * 0.125f); p[4]  = f2tf(qv.y * 0.125f);
        p[8]  = f2tf(qv.z * 0.125f); p[12] = f2tf(qv.w * 0.125f);
    }
    __syncthreads();

    // ---- hoist Q fragments to registers ----
    uint32_t qf[8][4];
    #pragma unroll
    for (int ks = 0; ks < 8; ks++) {
        uint4 t4 = *(const uint4*)&Qsf[warp][ks][lane][0];
        qf[ks][0] = t4.x; qf[ks][1] = t4.y; qf[ks][2] = t4.z; qf[ks][3] = t4.w;
    }

    float O[8][4];
    #pragma unroll
    for (int nt = 0; nt < 8; nt++)
        #pragma unroll
        for (int i = 0; i < 4; i++) O[nt][i] = 0.f;
    float m0r = -1e30f, m1r = -1e30f, l0 = 0.f, l1 = 0.f;

    const int base = qt * 128 + warp * 16;   // warp's first query row
    const int jmax = 2 * qt + 1;

    for (int j = 0; j <= jmax; j++) {
        // ---- stage K/V tile (64 keys x 64 dims each) ----
        float4 kR[4], vR[4];
        const float* Kt = Kg + (size_t)j * 64 * DK_;
        const float* Vt = Vg + (size_t)j * 64 * DK_;
        #pragma unroll
        for (int t = 0; t < 4; t++) {
            int idx = tid + t * 256, r = idx >> 4, c0 = (idx & 15) * 4;
            kR[t] = *(const float4*)&Kt[r * DK_ + c0];
            vR[t] = *(const float4*)&Vt[r * DK_ + c0];
        }
        __syncthreads();   // prior tile fully consumed
        #pragma unroll
        for (int t = 0; t < 4; t++) {
            int idx = tid + t * 256, r = idx >> 4, c0 = (idx & 15) * 4;
            {   // K: value K[r][c] -> Ksf[ks][nt][4g+tig][h]
                int nt = r >> 3, gk = r & 7;
                int ks = c0 >> 3, hh = (c0 >> 2) & 1;
                uint32_t* p = &Ksf[ks][nt][4 * gk][hh];
                p[0] = f2tf(kR[t].x); p[2] = f2tf(kR[t].y);
                p[4] = f2tf(kR[t].z); p[6] = f2tf(kR[t].w);
            }
            {   // V: value V[r][c] -> Vsf[kt][nt][4g+tig][h]
                int kt = r >> 3, rem = r & 7, tg = rem & 3, hh = rem >> 2;
                int nt = c0 >> 3, gv = c0 & 7;
                uint32_t* p = &Vsf[kt][nt][4 * gv + tg][hh];
                p[0] = f2tf(vR[t].x); p[8]  = f2tf(vR[t].y);
                p[16] = f2tf(vR[t].z); p[24] = f2tf(vR[t].w);
            }
        }
        __syncthreads();

        if (j * 64 > base + 15) continue;    // tile fully masked for this warp

        // ---- S = Q K^T ----
        float Sf[8][4];
        #pragma unroll
        for (int nt = 0; nt < 8; nt++)
            #pragma unroll
            for (int i = 0; i < 4; i++) Sf[nt][i] = 0.f;
        #pragma unroll
        for (int ks = 0; ks < 8; ks++) {
            #pragma unroll
            for (int nt = 0; nt < 8; nt++) {
                uint2 bf = *(const uint2*)&Ksf[ks][nt][lane][0];
                mma8(Sf[nt], qf[ks], (const uint32_t*)&bf);
            }
        }

        // ---- causal mask (tiles that touch the diagonal) ----
        if ((j + 1) * 64 > base) {
            int r0 = base + g - j * 64, r1 = r0 + 8;
            #pragma unroll
            for (int nt = 0; nt < 8; nt++) {
                int c0 = nt * 8 + 2 * tig, c1 = c0 + 1;
                if (c0 > r0) Sf[nt][0] = -1e30f;
                if (c1 > r0) Sf[nt][1] = -1e30f;
                if (c0 > r1) Sf[nt][2] = -1e30f;
                if (c1 > r1) Sf[nt][3] = -1e30f;
            }
        }

        // ---- online softmax ----
        float mx0 = -1e30f, mx1 = -1e30f;
        #pragma unroll
        for (int nt = 0; nt < 8; nt++) {
            mx0 = fmaxf(mx0, fmaxf(Sf[nt][0], Sf[nt][1]));
            mx1 = fmaxf(mx1, fmaxf(Sf[nt][2], Sf[nt][3]));
        }
        mx0 = fmaxf(mx0, __shfl_xor_sync(0xffffffffu, mx0, 1));
        mx0 = fmaxf(mx0, __shfl_xor_sync(0xffffffffu, mx0, 2));
        mx1 = fmaxf(mx1, __shfl_xor_sync(0xffffffffu, mx1, 1));
        mx1 = fmaxf(mx1, __shfl_xor_sync(0xffffffffu, mx1, 2));
        const float mn0 = fmaxf(m0r, mx0), mn1 = fmaxf(m1r, mx1);
        const float f0 = __expf(m0r - mn0), f1 = __expf(m1r - mn1);
        float s0 = 0.f, s1 = 0.f;
        const int rr = warp * 16 + g;
        #pragma unroll
        for (int nt = 0; nt < 8; nt++) {
            float p0 = __expf(Sf[nt][0] - mn0), p1 = __expf(Sf[nt][1] - mn0);
            float p2 = __expf(Sf[nt][2] - mn1), p3 = __expf(Sf[nt][3] - mn1);
            s0 += p0 + p1; s1 += p2 + p3;
            int cc = nt * 8 + 2 * tig;
            *(uint2*)&Ps[rr][cc]     = make_uint2(f2tf(p0), f2tf(p1));
            *(uint2*)&Ps[rr + 8][cc] = make_uint2(f2tf(p2), f2tf(p3));
            O[nt][0] *= f0; O[nt][1] *= f0;
            O[nt][2] *= f1; O[nt][3] *= f1;
        }
        s0 += __shfl_xor_sync(0xffffffffu, s0, 1);
        s0 += __shfl_xor_sync(0xffffffffu, s0, 2);
        s1 += __shfl_xor_sync(0xffffffffu, s1, 1);
        s1 += __shfl_xor_sync(0xffffffffu, s1, 2);
        l0 = l0 * f0 + s0; l1 = l1 * f1 + s1;
        m0r = mn0; m1r = mn1;
        __syncwarp();   // each warp consumes only its own P rows

        // ---- O += P V ----
        #pragma unroll
        for (int kt = 0; kt < 8; kt++) {
            uint32_t af[4];
            af[0] = Ps[rr][kt * 8 + tig];
            af[1] = Ps[rr + 8][kt * 8 + tig];
            af[2] = Ps[rr][kt * 8 + tig + 4];
            af[3] = Ps[rr + 8][kt * 8 + tig + 4];
            #pragma unroll
            for (int nt = 0; nt < 8; nt++) {
                uint2 bf = *(const uint2*)&Vsf[kt][nt][lane][0];
                mma8(O[nt], af, (const uint32_t*)&bf);
            }
        }
    }

    const float rl0 = 1.f / l0, rl1 = 1.f / l1;
    const int row0 = base + g;
    float* xp0 = g_X + ((size_t)b * S_ + row0) * (H_ * DV_) + h * DV_;
    float* xp1 = xp0 + (size_t)8 * (H_ * DV_);
    #pragma unroll
    for (int nt = 0; nt < 8; nt++) {
        int cc = nt * 8 + 2 * tig;
        *(float2*)&xp0[cc] = make_float2(O[nt][0] * rl0, O[nt][1] * rl0);
        *(float2*)&xp1[cc] = make_float2(O[nt][2] * rl1, O[nt][3] * rl1);
    }
}

// ---------------------------------------------------------------------------
// Kernel 3: output projection  y[m,d] = sum_e X[m,e] * Wo[d,e]
// Same fragment-major single-sync pipeline; B (=Wo) is K-contiguous.
// ---------------------------------------------------------------------------
__global__ __launch_bounds__(256) void out_proj_mma(
    const float* __restrict__ Wo, float* __restrict__ y)
{
    const int m0 = blockIdx.x * 128;
    const int n0 = blockIdx.y * 64;

    __shared__ uint32_t Asf[2][8][4][32][4];   // 32 KB
    __shared__ uint32_t Bsf[2][4][8][32][2];   // 16 KB

    const int tid = threadIdx.x, lane = tid & 31, warp = tid >> 5;
    const int wm = warp & 3, wn = warp >> 2;

    float acc[2][4][4];
    #pragma unroll
    for (int mt = 0; mt < 2; mt++)
        #pragma unroll
        for (int nt = 0; nt < 4; nt++)
            #pragma unroll
            for (int i = 0; i < 4; i++) acc[mt][nt][i] = 0.f;

    float4 aR[4], bR[2];
    auto loadG = [&](int k0) {
        #pragma unroll
        for (int t = 0; t < 4; t++) {
            int idx = tid + t * 256, r = idx >> 3, c = (idx & 7) * 4;
            aR[t] = *(const float4*)&g_X[(size_t)(m0 + r) * DM_ + k0 + c];
        }
        #pragma unroll
        for (int t = 0; t < 2; t++) {
            int idx = tid + t * 256, r = idx >> 3, c = (idx & 7) * 4;
            bR[t] = *(const float4*)&Wo[(size_t)(n0 + r) * DM_ + k0 + c];
        }
    };

    loadG(0);

    for (int it = 0; it < DM_ / 32; it++) {
        const int buf = it & 1;
        #pragma unroll
        for (int t = 0; t < 4; t++) {
            int idx = tid + t * 256, r = idx >> 3, c0 = (idx & 7) * 4;
            int mtg = r >> 4, rin = r & 15, gg = rin & 7, mh = rin >> 3;
            int ks = c0 >> 3, hh = (c0 >> 2) & 1;
            uint32_t* p = &Asf[buf][mtg][ks][4 * gg][mh + 2 * hh];
            p[0]  = f2tf(aR[t].x); p[4]  = f2tf(aR[t].y);
            p[8]  = f2tf(aR[t].z); p[12] = f2tf(aR[t].w);
        }
        #pragma unroll
        for (int t = 0; t < 2; t++) {
            // value Wo[n = n0 + r][k = k0 + c]:  Bsf[ks][nb][4g+tig][h]
            int idx = tid + t * 256, r = idx >> 3, c0 = (idx & 7) * 4;
            int nb = r >> 3, gg = r & 7;
            int ks = c0 >> 3, hh = (c0 >> 2) & 1;
            uint32_t* p = &Bsf[buf][ks][nb][4 * gg][hh];
            p[0] = f2tf(bR[t].x); p[2] = f2tf(bR[t].y);
            p[4] = f2tf(bR[t].z); p[6] = f2tf(bR[t].w);
        }
        __syncthreads();
        if (it + 1 < DM_ / 32) loadG((it + 1) * 32);

        #pragma unroll
        for (int ks = 0; ks < 4; ks++) {
            uint4 afA = *(const uint4*)&Asf[buf][wm * 2 + 0][ks][lane][0];
            uint4 afB = *(const uint4*)&Asf[buf][wm * 2 + 1][ks][lane][0];
            #pragma unroll
            for (int nt = 0; nt < 4; nt++) {
                uint2 bf = *(const uint2*)&Bsf[buf][ks][wn * 4 + nt][lane][0];
                mma8(acc[0][nt], (const uint32_t*)&afA, (const uint32_t*)&bf);
                mma8(acc[1][nt], (const uint32_t*)&afB, (const uint32_t*)&bf);
            }
        }
    }

    const int g = lane >> 2, tig = lane & 3;
    #pragma unroll
    for (int mt = 0; mt < 2; mt++) {
        #pragma unroll
        for (int half = 0; half < 2; half++) {
            int m = m0 + wm * 32 + mt * 16 + g + half * 8;
            #pragma unroll
            for (int nt = 0; nt < 4; nt++) {
                int nn = wn * 32 + nt * 8 + 2 * tig;
                float2 val = half ? make_float2(acc[mt][nt][2], acc[mt][nt][3])
                                  : make_float2(acc[mt][nt][0], acc[mt][nt][1]);
                *(float2*)&y[(size_t)m * DM_ + n0 + nn] = val;
            }
        }
    }
}

// ---------------------------------------------------------------------------
extern "C" void kernel_launch(void* const* d_in, const int* in_sizes, int n_in,
                              void* d_out, int out_size)
{
    const float* q  = (const float*)d_in[0];
    const float* k  = (const float*)d_in[1];
    const float* v  = (const float*)d_in[2];
    const float* Wq = (const float*)d_in[3];
    const float* Wk = (const float*)d_in[4];
    const float* Wv = (const float*)d_in[5];
    const float* Wo = (const float*)d_in[6];
    float* y = (float*)d_out;

    const int attn_smem = 16896 * (int)sizeof(uint32_t);   // 67584 B
    cudaFuncSetAttribute(attn_mma, cudaFuncAttributeMaxDynamicSharedMemorySize, attn_smem);

    qkv_proj_mma<<<dim3(S_ * B_ / 128, H_, 3), 256>>>(q, k, v, Wq, Wk, Wv);
    attn_mma<<<dim3(8, B_ * H_), 256, attn_smem>>>();
    out_proj_mma<<<dim3(S_ * B_ / 128, DM_ / 64), 256>>>(Wo, y);
}

// round 5
// speedup vs baseline: 2.0160x; 2.0160x over previous
#include <cuda_runtime.h>
#include <math.h>
#include <stdint.h>

static constexpr int B_ = 4, S_ = 1024, DM_ = 1024, H_ = 16, DK_ = 64, DV_ = 64;

// Scratch (device globals: no allocation allowed)
__device__ float g_Q[B_*H_*S_*DK_];     // [b,h,s,dk]
__device__ float g_K[B_*H_*S_*DK_];
__device__ float g_V[B_*H_*S_*DV_];
__device__ float g_X[B_*S_*H_*DV_];     // attn out, concat heads: [b,s,h*dv]

__device__ __forceinline__ uint32_t f2tf(float x) {
    uint32_t r;
    asm("cvt.rna.tf32.f32 %0, %1;" : "=r"(r) : "f"(x));
    return r;
}

// D += A * B  (m16n8k8, tf32 inputs, f32 accumulate)
__device__ __forceinline__ void mma8(float* c, const uint32_t* a, const uint32_t* b) {
    asm volatile(
        "mma.sync.aligned.m16n8k8.row.col.f32.tf32.tf32.f32 "
        "{%0,%1,%2,%3}, {%4,%5,%6,%7}, {%8,%9}, {%0,%1,%2,%3};"
        : "+f"(c[0]), "+f"(c[1]), "+f"(c[2]), "+f"(c[3])
        : "r"(a[0]), "r"(a[1]), "r"(a[2]), "r"(a[3]), "r"(b[0]), "r"(b[1]));
}

// ---------------------------------------------------------------------------
// Kernel 1: fused QKV projections. Block 128(M) x 64(N), 128 thr = 4 warps,
// warp tile 32x64, K-chunk 32. Plain smem layouts (R1-proven strides).
// ---------------------------------------------------------------------------
__global__ __launch_bounds__(128, 3) void qkv_proj_mma(
    const float* __restrict__ q, const float* __restrict__ k, const float* __restrict__ v,
    const float* __restrict__ Wq, const float* __restrict__ Wk, const float* __restrict__ Wv)
{
    const float* x; const float* W; float* out;
    if (blockIdx.z == 0)      { x = q; W = Wq; out = g_Q; }
    else if (blockIdx.z == 1) { x = k; W = Wk; out = g_K; }
    else                      { x = v; W = Wv; out = g_V; }

    const int m0 = blockIdx.x * 128;
    const int h  = blockIdx.y;
    const float* Wh = W + (size_t)h * DM_ * DK_;

    __shared__ uint32_t As[128][36];   // [m][k-chunk(32)]  frag addr: 4g+tig
    __shared__ uint32_t Bs[32][72];    // [k-chunk][n(64)]  frag addr: 8tig+g

    const int tid = threadIdx.x, lane = tid & 31, warp = tid >> 5;
    const int g = lane >> 2, tig = lane & 3;

    float acc[2][8][4];
    #pragma unroll
    for (int mt = 0; mt < 2; mt++)
        #pragma unroll
        for (int nt = 0; nt < 8; nt++)
            #pragma unroll
            for (int i = 0; i < 4; i++) acc[mt][nt][i] = 0.f;

    float4 aR[8], bR[4];
    auto loadG = [&](int k0) {
        #pragma unroll
        for (int t = 0; t < 8; t++) {
            int idx = tid + t * 128, r = idx >> 3, c = (idx & 7) * 4;
            aR[t] = *(const float4*)&x[(size_t)(m0 + r) * DM_ + k0 + c];
        }
        #pragma unroll
        for (int t = 0; t < 4; t++) {
            int idx = tid + t * 128, r = idx >> 4, c = (idx & 15) * 4;
            bR[t] = *(const float4*)&Wh[(size_t)(k0 + r) * DK_ + c];
        }
    };

    loadG(0);

    for (int it = 0; it < DM_ / 32; it++) {
        __syncthreads();   // prior compute done reading smem
        #pragma unroll
        for (int t = 0; t < 8; t++) {
            int idx = tid + t * 128, r = idx >> 3, c = (idx & 7) * 4;   // c<=28
            As[r][c]   = f2tf(aR[t].x); As[r][c+1] = f2tf(aR[t].y);
            As[r][c+2] = f2tf(aR[t].z); As[r][c+3] = f2tf(aR[t].w);
        }
        #pragma unroll
        for (int t = 0; t < 4; t++) {
            int idx = tid + t * 128, r = idx >> 4, c = (idx & 15) * 4;  // c<=60
            Bs[r][c]   = f2tf(bR[t].x); Bs[r][c+1] = f2tf(bR[t].y);
            Bs[r][c+2] = f2tf(bR[t].z); Bs[r][c+3] = f2tf(bR[t].w);
        }
        __syncthreads();
        if (it + 1 < DM_ / 32) loadG((it + 1) * 32);   // overlap with compute

        #pragma unroll
        for (int ks = 0; ks < 4; ks++) {
            uint32_t af[2][4];
            #pragma unroll
            for (int mt = 0; mt < 2; mt++) {
                int rr = warp * 32 + mt * 16 + g;
                af[mt][0] = As[rr][ks*8 + tig];
                af[mt][1] = As[rr + 8][ks*8 + tig];
                af[mt][2] = As[rr][ks*8 + tig + 4];
                af[mt][3] = As[rr + 8][ks*8 + tig + 4];
            }
            #pragma unroll
            for (int nt = 0; nt < 8; nt++) {
                uint32_t bf[2];
                bf[0] = Bs[ks*8 + tig][nt*8 + g];
                bf[1] = Bs[ks*8 + tig + 4][nt*8 + g];
                mma8(acc[0][nt], af[0], bf);
                mma8(acc[1][nt], af[1], bf);
            }
        }
    }

    #pragma unroll
    for (int mt = 0; mt < 2; mt++) {
        #pragma unroll
        for (int half = 0; half < 2; half++) {
            int m = m0 + warp * 32 + mt * 16 + g + half * 8;
            int b = m >> 10, s = m & 1023;
            float* op = &out[(((size_t)b * H_ + h) * S_ + s) * DK_];
            #pragma unroll
            for (int nt = 0; nt < 8; nt++) {
                int nn = nt * 8 + 2 * tig;
                float2 val = half ? make_float2(acc[mt][nt][2], acc[mt][nt][3])
                                  : make_float2(acc[mt][nt][0], acc[mt][nt][1]);
                *(float2*)&op[nn] = val;
            }
        }
    }
}

// ---------------------------------------------------------------------------
// Kernel 2: causal flash attention. 128 thr = 4 warps; block = 128 query rows,
// warp = 32 rows. 64-key tiles. Strides 68/72 (64 data cols + pad), all
// fragment accesses conflict-free (R1-proven patterns).
// ---------------------------------------------------------------------------
__global__ __launch_bounds__(128, 2) void attn_mma()
{
    extern __shared__ uint32_t sm[];
    uint32_t (*Qs)[68] = (uint32_t(*)[68])sm;                              // 128x68
    uint32_t (*Ks)[68] = (uint32_t(*)[68])(sm + 128*68);                   // 64x68
    uint32_t (*Vs)[72] = (uint32_t(*)[72])(sm + 128*68 + 64*68);           // 64x72
    uint32_t (*Ps)[68] = (uint32_t(*)[68])(sm + 128*68 + 64*68 + 64*72);   // 128x68

    const int qt = 7 - blockIdx.x;          // descending work for tail balance
    const int bh = blockIdx.y;
    const int b = bh >> 4, h = bh & 15;
    const int tid = threadIdx.x, lane = tid & 31, warp = tid >> 5;
    const int g = lane >> 2, tig = lane & 3;

    const float* Qg = g_Q + (size_t)bh * S_ * DK_ + (size_t)qt * 128 * DK_;
    const float* Kg = g_K + (size_t)bh * S_ * DK_;
    const float* Vg = g_V + (size_t)bh * S_ * DK_;

    // ---- stage Q tile (scaled by 1/8, tf32) ----
    #pragma unroll
    for (int t = 0; t < 16; t++) {
        int idx = tid + t * 128, r = idx >> 4, c = (idx & 15) * 4;   // r<128, c<=60
        float4 qv = *(const float4*)&Qg[r * DK_ + c];
        Qs[r][c]   = f2tf(qv.x * 0.125f); Qs[r][c+1] = f2tf(qv.y * 0.125f);
        Qs[r][c+2] = f2tf(qv.z * 0.125f); Qs[r][c+3] = f2tf(qv.w * 0.125f);
    }

    float O[2][8][4];
    #pragma unroll
    for (int mt = 0; mt < 2; mt++)
        #pragma unroll
        for (int nt = 0; nt < 8; nt++)
            #pragma unroll
            for (int i = 0; i < 4; i++) O[mt][nt][i] = 0.f;
    float mst[2][2] = {{-1e30f,-1e30f},{-1e30f,-1e30f}};
    float lst[2][2] = {{0.f,0.f},{0.f,0.f}};

    const int base = qt * 128 + warp * 32;   // warp's first query row (global)
    const int jmax = 2 * qt + 1;

    for (int j = 0; j <= jmax; j++) {
        const float* Kt = Kg + (size_t)j * 64 * DK_;
        const float* Vt = Vg + (size_t)j * 64 * DK_;
        __syncthreads();   // prior tile fully consumed (also orders Q staging)
        #pragma unroll
        for (int t = 0; t < 8; t++) {
            int idx = tid + t * 128, r = idx >> 4, c = (idx & 15) * 4;  // r<64
            float4 kv = *(const float4*)&Kt[r * DK_ + c];
            float4 vv = *(const float4*)&Vt[r * DK_ + c];
            Ks[r][c]   = f2tf(kv.x); Ks[r][c+1] = f2tf(kv.y);
            Ks[r][c+2] = f2tf(kv.z); Ks[r][c+3] = f2tf(kv.w);
            Vs[r][c]   = f2tf(vv.x); Vs[r][c+1] = f2tf(vv.y);
            Vs[r][c+2] = f2tf(vv.z); Vs[r][c+3] = f2tf(vv.w);
        }
        __syncthreads();

        if (j * 64 > base + 31) continue;    // tile fully masked for this warp

        // ---- S = Q K^T  (32 rows x 64 keys per warp) ----
        float Sf[2][8][4];
        #pragma unroll
        for (int mt = 0; mt < 2; mt++)
            #pragma unroll
            for (int nt = 0; nt < 8; nt++)
                #pragma unroll
                for (int i = 0; i < 4; i++) Sf[mt][nt][i] = 0.f;

        #pragma unroll
        for (int ks = 0; ks < 8; ks++) {
            uint32_t af[2][4];
            #pragma unroll
            for (int mt = 0; mt < 2; mt++) {
                int rr = warp * 32 + mt * 16 + g;
                af[mt][0] = Qs[rr][ks*8 + tig];
                af[mt][1] = Qs[rr + 8][ks*8 + tig];
                af[mt][2] = Qs[rr][ks*8 + tig + 4];
                af[mt][3] = Qs[rr + 8][ks*8 + tig + 4];
            }
            #pragma unroll
            for (int nt = 0; nt < 8; nt++) {
                uint32_t bf[2];
                bf[0] = Ks[nt*8 + g][ks*8 + tig];
                bf[1] = Ks[nt*8 + g][ks*8 + tig + 4];
                mma8(Sf[0][nt], af[0], bf);
                mma8(Sf[1][nt], af[1], bf);
            }
        }

        // ---- causal mask (tiles touching the diagonal) ----
        if ((j + 1) * 64 > base) {
            #pragma unroll
            for (int mt = 0; mt < 2; mt++) {
                int r0 = base + mt * 16 + g - j * 64, r1 = r0 + 8;
                #pragma unroll
                for (int nt = 0; nt < 8; nt++) {
                    int c0 = nt * 8 + 2 * tig, c1 = c0 + 1;
                    if (c0 > r0) Sf[mt][nt][0] = -1e30f;
                    if (c1 > r0) Sf[mt][nt][1] = -1e30f;
                    if (c0 > r1) Sf[mt][nt][2] = -1e30f;
                    if (c1 > r1) Sf[mt][nt][3] = -1e30f;
                }
            }
        }

        // ---- online softmax over 4 row-groups (mt x rowpair) ----
        #pragma unroll
        for (int mt = 0; mt < 2; mt++) {
            #pragma unroll
            for (int hp = 0; hp < 2; hp++) {
                float mx = -1e30f;
                #pragma unroll
                for (int nt = 0; nt < 8; nt++)
                    mx = fmaxf(mx, fmaxf(Sf[mt][nt][2*hp], Sf[mt][nt][2*hp+1]));
                mx = fmaxf(mx, __shfl_xor_sync(0xffffffffu, mx, 1));
                mx = fmaxf(mx, __shfl_xor_sync(0xffffffffu, mx, 2));
                const float mn = fmaxf(mst[mt][hp], mx);
                const float fac = __expf(mst[mt][hp] - mn);
                float ls = 0.f;
                const int rr = warp * 32 + mt * 16 + g + 8 * hp;
                #pragma unroll
                for (int nt = 0; nt < 8; nt++) {
                    float p0 = __expf(Sf[mt][nt][2*hp]     - mn);
                    float p1 = __expf(Sf[mt][nt][2*hp + 1] - mn);
                    ls += p0 + p1;
                    *(uint2*)&Ps[rr][nt*8 + 2*tig] = make_uint2(f2tf(p0), f2tf(p1));
                    O[mt][nt][2*hp]     *= fac;
                    O[mt][nt][2*hp + 1] *= fac;
                }
                ls += __shfl_xor_sync(0xffffffffu, ls, 1);
                ls += __shfl_xor_sync(0xffffffffu, ls, 2);
                lst[mt][hp] = lst[mt][hp] * fac + ls;
                mst[mt][hp] = mn;
            }
        }
        __syncwarp();   // each warp consumes only its own P rows

        // ---- O += P V ----
        #pragma unroll
        for (int kt = 0; kt < 8; kt++) {
            uint32_t af[2][4];
            #pragma unroll
            for (int mt = 0; mt < 2; mt++) {
                int rr = warp * 32 + mt * 16 + g;
                af[mt][0] = Ps[rr][kt*8 + tig];
                af[mt][1] = Ps[rr + 8][kt*8 + tig];
                af[mt][2] = Ps[rr][kt*8 + tig + 4];
                af[mt][3] = Ps[rr + 8][kt*8 + tig + 4];
            }
            #pragma unroll
            for (int nt = 0; nt < 8; nt++) {
                uint32_t bf[2];
                bf[0] = Vs[kt*8 + tig][nt*8 + g];
                bf[1] = Vs[kt*8 + tig + 4][nt*8 + g];
                mma8(O[0][nt], af[0], bf);
                mma8(O[1][nt], af[1], bf);
            }
        }
    }

    #pragma unroll
    for (int mt = 0; mt < 2; mt++) {
        #pragma unroll
        for (int hp = 0; hp < 2; hp++) {
            const float rl = 1.f / lst[mt][hp];
            const int row = base + mt * 16 + g + 8 * hp;
            float* xp = g_X + ((size_t)b * S_ + row) * (H_ * DV_) + h * DV_;
            #pragma unroll
            for (int nt = 0; nt < 8; nt++) {
                int cc = nt * 8 + 2 * tig;
                *(float2*)&xp[cc] = make_float2(O[mt][nt][2*hp] * rl,
                                                O[mt][nt][2*hp + 1] * rl);
            }
        }
    }
}

// ---------------------------------------------------------------------------
// Kernel 3: output projection  y[m,d] = sum_e X[m,e] * Wo[d,e]
// Block 128x64, 4 warps, warp 32x64. B (=Wo) rows are K-contiguous -> [n][k].
// ---------------------------------------------------------------------------
__global__ __launch_bounds__(128, 3) void out_proj_mma(
    const float* __restrict__ Wo, float* __restrict__ y)
{
    const int m0 = blockIdx.x * 128;
    const int n0 = blockIdx.y * 64;

    __shared__ uint32_t As [128][36];   // [m][k-chunk]
    __shared__ uint32_t Bsn[64][36];    // [n][k-chunk]  frag addr: 4g+tig

    const int tid = threadIdx.x, lane = tid & 31, warp = tid >> 5;
    const int g = lane >> 2, tig = lane & 3;

    float acc[2][8][4];
    #pragma unroll
    for (int mt = 0; mt < 2; mt++)
        #pragma unroll
        for (int nt = 0; nt < 8; nt++)
            #pragma unroll
            for (int i = 0; i < 4; i++) acc[mt][nt][i] = 0.f;

    float4 aR[8], bR[4];
    auto loadG = [&](int k0) {
        #pragma unroll
        for (int t = 0; t < 8; t++) {
            int idx = tid + t * 128, r = idx >> 3, c = (idx & 7) * 4;
            aR[t] = *(const float4*)&g_X[(size_t)(m0 + r) * DM_ + k0 + c];
        }
        #pragma unroll
        for (int t = 0; t < 4; t++) {
            int idx = tid + t * 128, r = idx >> 3, c = (idx & 7) * 4;
            bR[t] = *(const float4*)&Wo[(size_t)(n0 + r) * DM_ + k0 + c];
        }
    };

    loadG(0);

    for (int it = 0; it < DM_ / 32; it++) {
        __syncthreads();
        #pragma unroll
        for (int t = 0; t < 8; t++) {
            int idx = tid + t * 128, r = idx >> 3, c = (idx & 7) * 4;   // c<=28
            As[r][c]   = f2tf(aR[t].x); As[r][c+1] = f2tf(aR[t].y);
            As[r][c+2] = f2tf(aR[t].z); As[r][c+3] = f2tf(aR[t].w);
        }
        #pragma unroll
        for (int t = 0; t < 4; t++) {
            int idx = tid + t * 128, r = idx >> 3, c = (idx & 7) * 4;   // r<64
            Bsn[r][c]   = f2tf(bR[t].x); Bsn[r][c+1] = f2tf(bR[t].y);
            Bsn[r][c+2] = f2tf(bR[t].z); Bsn[r][c+3] = f2tf(bR[t].w);
        }
        __syncthreads();
        if (it + 1 < DM_ / 32) loadG((it + 1) * 32);

        #pragma unroll
        for (int ks = 0; ks < 4; ks++) {
            uint32_t af[2][4];
            #pragma unroll
            for (int mt = 0; mt < 2; mt++) {
                int rr = warp * 32 + mt * 16 + g;
                af[mt][0] = As[rr][ks*8 + tig];
                af[mt][1] = As[rr + 8][ks*8 + tig];
                af[mt][2] = As[rr][ks*8 + tig + 4];
                af[mt][3] = As[rr + 8][ks*8 + tig + 4];
            }
            #pragma unroll
            for (int nt = 0; nt < 8; nt++) {
                uint32_t bf[2];
                bf[0] = Bsn[nt*8 + g][ks*8 + tig];
                bf[1] = Bsn[nt*8 + g][ks*8 + tig + 4];
                mma8(acc[0][nt], af[0], bf);
                mma8(acc[1][nt], af[1], bf);
            }
        }
    }

    #pragma unroll
    for (int mt = 0; mt < 2; mt++) {
        #pragma unroll
        for (int half = 0; half < 2; half++) {
            int m = m0 + warp * 32 + mt * 16 + g + half * 8;
            #pragma unroll
            for (int nt = 0; nt < 8; nt++) {
                int nn = nt * 8 + 2 * tig;
                float2 val = half ? make_float2(acc[mt][nt][2], acc[mt][nt][3])
                                  : make_float2(acc[mt][nt][0], acc[mt][nt][1]);
                *(float2*)&y[(size_t)m * DM_ + n0 + nn] = val;
            }
        }
    }
}

// ---------------------------------------------------------------------------
extern "C" void kernel_launch(void* const* d_in, const int* in_sizes, int n_in,
                              void* d_out, int out_size)
{
    const float* q  = (const float*)d_in[0];
    const float* k  = (const float*)d_in[1];
    const float* v  = (const float*)d_in[2];
    const float* Wq = (const float*)d_in[3];
    const float* Wk = (const float*)d_in[4];
    const float* Wv = (const float*)d_in[5];
    const float* Wo = (const float*)d_in[6];
    float* y = (float*)d_out;

    // attn smem: Qs 128x68 + Ks 64x68 + Vs 64x72 + Ps 128x68 words = 105472 B
    const int attn_smem = (128*68 + 64*68 + 64*72 + 128*68) * (int)sizeof(uint32_t);
    cudaFuncSetAttribute(attn_mma, cudaFuncAttributeMaxDynamicSharedMemorySize, attn_smem);

    qkv_proj_mma<<<dim3(S_ * B_ / 128, H_, 3), 128>>>(q, k, v, Wq, Wk, Wv);
    attn_mma<<<dim3(8, B_ * H_), 128, attn_smem>>>();
    out_proj_mma<<<dim3(S_ * B_ / 128, DM_ / 64), 128>>>(Wo, y);
}

// round 6
// speedup vs baseline: 2.2502x; 1.1162x over previous
#include <cuda_runtime.h>
#include <math.h>
#include <stdint.h>

static constexpr int B_ = 4, S_ = 1024, DM_ = 1024, H_ = 16, DK_ = 64, DV_ = 64;
static constexpr int NX_ = B_*S_*DM_;     // 4M elements (q/k/v)
static constexpr int NW_ = H_*DM_*DK_;    // 1M elements (Wq/Wk/Wv)
static constexpr int NWO_ = DM_*H_*DV_;   // 1M elements (Wo)

// Scratch (device globals: no allocation allowed). All tf32 bit patterns.
__device__ uint32_t g_qT[NX_], g_kT[NX_], g_vT[NX_];
__device__ uint32_t g_WqT[NW_], g_WkT[NW_], g_WvT[NW_], g_WoT[NWO_];
__device__ uint32_t g_Q[B_*H_*S_*DK_];    // [b,h,s,dk], pre-scaled by 1/8
__device__ uint32_t g_K[B_*H_*S_*DK_];
__device__ uint32_t g_V[B_*H_*S_*DV_];
__device__ uint32_t g_X[B_*S_*H_*DV_];    // attn out concat heads [b,s,h*dv]

__device__ __forceinline__ uint32_t f2tf(float x) {
    uint32_t r;
    asm("cvt.rna.tf32.f32 %0, %1;" : "=r"(r) : "f"(x));
    return r;
}

// D += A * B  (m16n8k8, tf32 inputs, f32 accumulate)
__device__ __forceinline__ void mma8(float* c, const uint32_t* a, const uint32_t* b) {
    asm volatile(
        "mma.sync.aligned.m16n8k8.row.col.f32.tf32.tf32.f32 "
        "{%0,%1,%2,%3}, {%4,%5,%6,%7}, {%8,%9}, {%0,%1,%2,%3};"
        : "+f"(c[0]), "+f"(c[1]), "+f"(c[2]), "+f"(c[3])
        : "r"(a[0]), "r"(a[1]), "r"(a[2]), "r"(a[3]), "r"(b[0]), "r"(b[1]));
}

__device__ __forceinline__ void cpa16(void* smem_ptr, const void* gptr) {
    uint32_t s = (uint32_t)__cvta_generic_to_shared(smem_ptr);
    asm volatile("cp.async.cg.shared.global [%0], [%1], 16;" :: "r"(s), "l"(gptr));
}
__device__ __forceinline__ void cpa_commit() { asm volatile("cp.async.commit_group;"); }
__device__ __forceinline__ void cpa_wait0()  { asm volatile("cp.async.wait_group 0;"); }

// ---------------------------------------------------------------------------
// Kernel 0: one-time conversion of all inputs to tf32 bit patterns.
// ---------------------------------------------------------------------------
__global__ __launch_bounds__(256) void cvt_inputs(
    const float* __restrict__ q, const float* __restrict__ k, const float* __restrict__ v,
    const float* __restrict__ Wq, const float* __restrict__ Wk, const float* __restrict__ Wv,
    const float* __restrict__ Wo)
{
    const float* src; uint32_t* dst; int n;
    switch (blockIdx.y) {
        case 0: src = q;  dst = g_qT;  n = NX_;  break;
        case 1: src = k;  dst = g_kT;  n = NX_;  break;
        case 2: src = v;  dst = g_vT;  n = NX_;  break;
        case 3: src = Wq; dst = g_WqT; n = NW_;  break;
        case 4: src = Wk; dst = g_WkT; n = NW_;  break;
        case 5: src = Wv; dst = g_WvT; n = NW_;  break;
        default: src = Wo; dst = g_WoT; n = NWO_; break;
    }
    int i = (blockIdx.x * 256 + threadIdx.x) * 4;
    if (i < n) {
        float4 vl = *(const float4*)&src[i];
        *(uint4*)&dst[i] = make_uint4(f2tf(vl.x), f2tf(vl.y), f2tf(vl.z), f2tf(vl.w));
    }
}

// ---------------------------------------------------------------------------
// Kernel 1: fused QKV projections. Block 128(M) x 64(N), 4 warps, warp 32x64,
// K-chunk 32, cp.async double-buffered, one sync per chunk.
// ---------------------------------------------------------------------------
__global__ __launch_bounds__(128) void qkv_proj_mma()
{
    extern __shared__ uint32_t smq[];
    uint32_t (*As)[128][36] = (uint32_t(*)[128][36])smq;              // 2 bufs
    uint32_t (*Bs)[32][72]  = (uint32_t(*)[32][72])(smq + 2*128*36);

    const uint32_t* x; const uint32_t* W; uint32_t* out; float sc = 1.f;
    if (blockIdx.z == 0)      { x = g_qT; W = g_WqT; out = g_Q; sc = 0.125f; }
    else if (blockIdx.z == 1) { x = g_kT; W = g_WkT; out = g_K; }
    else                      { x = g_vT; W = g_WvT; out = g_V; }

    const int m0 = blockIdx.x * 128;
    const int h  = blockIdx.y;
    const uint32_t* Wh = W + (size_t)h * DM_ * DK_;

    const int tid = threadIdx.x, lane = tid & 31, warp = tid >> 5;
    const int g = lane >> 2, tig = lane & 3;

    float acc[2][8][4];
    #pragma unroll
    for (int mt = 0; mt < 2; mt++)
        #pragma unroll
        for (int nt = 0; nt < 8; nt++)
            #pragma unroll
            for (int i = 0; i < 4; i++) acc[mt][nt][i] = 0.f;

    auto issue = [&](int k0, int buf) {
        #pragma unroll
        for (int t = 0; t < 8; t++) {
            int idx = tid + t * 128, r = idx >> 3, c = (idx & 7) * 4;
            cpa16(&As[buf][r][c], &x[(size_t)(m0 + r) * DM_ + k0 + c]);
        }
        #pragma unroll
        for (int t = 0; t < 4; t++) {
            int idx = tid + t * 128, r = idx >> 4, c = (idx & 15) * 4;
            cpa16(&Bs[buf][r][c], &Wh[(size_t)(k0 + r) * DK_ + c]);
        }
        cpa_commit();
    };

    issue(0, 0);

    for (int it = 0; it < DM_ / 32; it++) {
        const int buf = it & 1;
        cpa_wait0();
        __syncthreads();           // chunk it visible; prior compute finished
        if (it + 1 < DM_ / 32) issue((it + 1) * 32, buf ^ 1);

        #pragma unroll
        for (int ks = 0; ks < 4; ks++) {
            uint32_t af[2][4];
            #pragma unroll
            for (int mt = 0; mt < 2; mt++) {
                int rr = warp * 32 + mt * 16 + g;
                af[mt][0] = As[buf][rr][ks*8 + tig];
                af[mt][1] = As[buf][rr + 8][ks*8 + tig];
                af[mt][2] = As[buf][rr][ks*8 + tig + 4];
                af[mt][3] = As[buf][rr + 8][ks*8 + tig + 4];
            }
            #pragma unroll
            for (int nt = 0; nt < 8; nt++) {
                uint32_t bf[2];
                bf[0] = Bs[buf][ks*8 + tig][nt*8 + g];
                bf[1] = Bs[buf][ks*8 + tig + 4][nt*8 + g];
                mma8(acc[0][nt], af[0], bf);
                mma8(acc[1][nt], af[1], bf);
            }
        }
    }

    #pragma unroll
    for (int mt = 0; mt < 2; mt++) {
        #pragma unroll
        for (int half = 0; half < 2; half++) {
            int m = m0 + warp * 32 + mt * 16 + g + half * 8;
            int b = m >> 10, s = m & 1023;
            uint32_t* op = &out[(((size_t)b * H_ + h) * S_ + s) * DK_];
            #pragma unroll
            for (int nt = 0; nt < 8; nt++) {
                int nn = nt * 8 + 2 * tig;
                float v0 = half ? acc[mt][nt][2] : acc[mt][nt][0];
                float v1 = half ? acc[mt][nt][3] : acc[mt][nt][1];
                *(uint2*)&op[nn] = make_uint2(f2tf(v0 * sc), f2tf(v1 * sc));
            }
        }
    }
}

// ---------------------------------------------------------------------------
// Kernel 2: causal flash attention. 4 warps, 128-query tiles, 64-key tiles.
// Q/K/V arrive as tf32 bits (Q pre-scaled); staging via cp.async.
// ---------------------------------------------------------------------------
__global__ __launch_bounds__(128) void attn_mma()
{
    extern __shared__ uint32_t sm[];
    uint32_t (*Qs)[68] = (uint32_t(*)[68])sm;                              // 128x68
    uint32_t (*Ks)[68] = (uint32_t(*)[68])(sm + 128*68);                   // 64x68
    uint32_t (*Vs)[72] = (uint32_t(*)[72])(sm + 128*68 + 64*68);           // 64x72
    uint32_t (*Ps)[68] = (uint32_t(*)[68])(sm + 128*68 + 64*68 + 64*72);   // 128x68

    const int qt = 7 - blockIdx.x;          // descending work for tail balance
    const int bh = blockIdx.y;
    const int b = bh >> 4, h = bh & 15;
    const int tid = threadIdx.x, lane = tid & 31, warp = tid >> 5;
    const int g = lane >> 2, tig = lane & 3;

    const uint32_t* Qg = g_Q + (size_t)bh * S_ * DK_ + (size_t)qt * 128 * DK_;
    const uint32_t* Kg = g_K + (size_t)bh * S_ * DK_;
    const uint32_t* Vg = g_V + (size_t)bh * S_ * DK_;

    // stage Q tile (already tf32, already scaled)
    #pragma unroll
    for (int t = 0; t < 16; t++) {
        int idx = tid + t * 128, r = idx >> 4, c = (idx & 15) * 4;
        cpa16(&Qs[r][c], &Qg[r * DK_ + c]);
    }
    cpa_commit();

    float O[2][8][4];
    #pragma unroll
    for (int mt = 0; mt < 2; mt++)
        #pragma unroll
        for (int nt = 0; nt < 8; nt++)
            #pragma unroll
            for (int i = 0; i < 4; i++) O[mt][nt][i] = 0.f;
    float mst[2][2] = {{-1e30f,-1e30f},{-1e30f,-1e30f}};
    float lst[2][2] = {{0.f,0.f},{0.f,0.f}};

    const int base = qt * 128 + warp * 32;
    const int jmax = 2 * qt + 1;

    for (int j = 0; j <= jmax; j++) {
        const uint32_t* Kt = Kg + (size_t)j * 64 * DK_;
        const uint32_t* Vt = Vg + (size_t)j * 64 * DK_;
        __syncthreads();           // prior tile fully consumed by all warps
        #pragma unroll
        for (int t = 0; t < 8; t++) {
            int idx = tid + t * 128, r = idx >> 4, c = (idx & 15) * 4;
            cpa16(&Ks[r][c], &Kt[r * DK_ + c]);
            cpa16(&Vs[r][c], &Vt[r * DK_ + c]);
        }
        cpa_commit();
        cpa_wait0();
        __syncthreads();

        if (j * 64 > base + 31) continue;    // tile fully masked for this warp

        // ---- S = Q K^T  (32 rows x 64 keys per warp) ----
        float Sf[2][8][4];
        #pragma unroll
        for (int mt = 0; mt < 2; mt++)
            #pragma unroll
            for (int nt = 0; nt < 8; nt++)
                #pragma unroll
                for (int i = 0; i < 4; i++) Sf[mt][nt][i] = 0.f;

        #pragma unroll
        for (int ks = 0; ks < 8; ks++) {
            uint32_t af[2][4];
            #pragma unroll
            for (int mt = 0; mt < 2; mt++) {
                int rr = warp * 32 + mt * 16 + g;
                af[mt][0] = Qs[rr][ks*8 + tig];
                af[mt][1] = Qs[rr + 8][ks*8 + tig];
                af[mt][2] = Qs[rr][ks*8 + tig + 4];
                af[mt][3] = Qs[rr + 8][ks*8 + tig + 4];
            }
            #pragma unroll
            for (int nt = 0; nt < 8; nt++) {
                uint32_t bf[2];
                bf[0] = Ks[nt*8 + g][ks*8 + tig];
                bf[1] = Ks[nt*8 + g][ks*8 + tig + 4];
                mma8(Sf[0][nt], af[0], bf);
                mma8(Sf[1][nt], af[1], bf);
            }
        }

        // ---- causal mask (tiles touching the diagonal) ----
        if ((j + 1) * 64 > base) {
            #pragma unroll
            for (int mt = 0; mt < 2; mt++) {
                int r0 = base + mt * 16 + g - j * 64, r1 = r0 + 8;
                #pragma unroll
                for (int nt = 0; nt < 8; nt++) {
                    int c0 = nt * 8 + 2 * tig, c1 = c0 + 1;
                    if (c0 > r0) Sf[mt][nt][0] = -1e30f;
                    if (c1 > r0) Sf[mt][nt][1] = -1e30f;
                    if (c0 > r1) Sf[mt][nt][2] = -1e30f;
                    if (c1 > r1) Sf[mt][nt][3] = -1e30f;
                }
            }
        }

        // ---- online softmax over 4 row-groups (mt x rowpair) ----
        #pragma unroll
        for (int mt = 0; mt < 2; mt++) {
            #pragma unroll
            for (int hp = 0; hp < 2; hp++) {
                float mx = -1e30f;
                #pragma unroll
                for (int nt = 0; nt < 8; nt++)
                    mx = fmaxf(mx, fmaxf(Sf[mt][nt][2*hp], Sf[mt][nt][2*hp+1]));
                mx = fmaxf(mx, __shfl_xor_sync(0xffffffffu, mx, 1));
                mx = fmaxf(mx, __shfl_xor_sync(0xffffffffu, mx, 2));
                const float mn = fmaxf(mst[mt][hp], mx);
                const float fac = __expf(mst[mt][hp] - mn);
                float ls = 0.f;
                const int rr = warp * 32 + mt * 16 + g + 8 * hp;
                #pragma unroll
                for (int nt = 0; nt < 8; nt++) {
                    float p0 = __expf(Sf[mt][nt][2*hp]     - mn);
                    float p1 = __expf(Sf[mt][nt][2*hp + 1] - mn);
                    ls += p0 + p1;
                    *(uint2*)&Ps[rr][nt*8 + 2*tig] = make_uint2(f2tf(p0), f2tf(p1));
                    O[mt][nt][2*hp]     *= fac;
                    O[mt][nt][2*hp + 1] *= fac;
                }
                ls += __shfl_xor_sync(0xffffffffu, ls, 1);
                ls += __shfl_xor_sync(0xffffffffu, ls, 2);
                lst[mt][hp] = lst[mt][hp] * fac + ls;
                mst[mt][hp] = mn;
            }
        }
        __syncwarp();   // each warp consumes only its own P rows

        // ---- O += P V ----
        #pragma unroll
        for (int kt = 0; kt < 8; kt++) {
            uint32_t af[2][4];
            #pragma unroll
            for (int mt = 0; mt < 2; mt++) {
                int rr = warp * 32 + mt * 16 + g;
                af[mt][0] = Ps[rr][kt*8 + tig];
                af[mt][1] = Ps[rr + 8][kt*8 + tig];
                af[mt][2] = Ps[rr][kt*8 + tig + 4];
                af[mt][3] = Ps[rr + 8][kt*8 + tig + 4];
            }
            #pragma unroll
            for (int nt = 0; nt < 8; nt++) {
                uint32_t bf[2];
                bf[0] = Vs[kt*8 + tig][nt*8 + g];
                bf[1] = Vs[kt*8 + tig + 4][nt*8 + g];
                mma8(O[0][nt], af[0], bf);
                mma8(O[1][nt], af[1], bf);
            }
        }
    }

    // epilogue: write X as tf32 bits (out_proj consumes it as mma operand)
    #pragma unroll
    for (int mt = 0; mt < 2; mt++) {
        #pragma unroll
        for (int hp = 0; hp < 2; hp++) {
            const float rl = 1.f / lst[mt][hp];
            const int row = base + mt * 16 + g + 8 * hp;
            uint32_t* xp = g_X + ((size_t)b * S_ + row) * (H_ * DV_) + h * DV_;
            #pragma unroll
            for (int nt = 0; nt < 8; nt++) {
                int cc = nt * 8 + 2 * tig;
                *(uint2*)&xp[cc] = make_uint2(f2tf(O[mt][nt][2*hp] * rl),
                                              f2tf(O[mt][nt][2*hp + 1] * rl));
            }
        }
    }
}

// ---------------------------------------------------------------------------
// Kernel 3: output projection  y[m,d] = sum_e X[m,e] * Wo[d,e]
// cp.async double-buffered; X and Wo already tf32 bits.
// ---------------------------------------------------------------------------
__global__ __launch_bounds__(128) void out_proj_mma(float* __restrict__ y)
{
    extern __shared__ uint32_t smo[];
    uint32_t (*As)[128][36]  = (uint32_t(*)[128][36])smo;
    uint32_t (*Bsn)[64][36]  = (uint32_t(*)[64][36])(smo + 2*128*36);

    const int m0 = blockIdx.x * 128;
    const int n0 = blockIdx.y * 64;

    const int tid = threadIdx.x, lane = tid & 31, warp = tid >> 5;
    const int g = lane >> 2, tig = lane & 3;

    float acc[2][8][4];
    #pragma unroll
    for (int mt = 0; mt < 2; mt++)
        #pragma unroll
        for (int nt = 0; nt < 8; nt++)
            #pragma unroll
            for (int i = 0; i < 4; i++) acc[mt][nt][i] = 0.f;

    auto issue = [&](int k0, int buf) {
        #pragma unroll
        for (int t = 0; t < 8; t++) {
            int idx = tid + t * 128, r = idx >> 3, c = (idx & 7) * 4;
            cpa16(&As[buf][r][c], &g_X[(size_t)(m0 + r) * DM_ + k0 + c]);
        }
        #pragma unroll
        for (int t = 0; t < 4; t++) {
            int idx = tid + t * 128, r = idx >> 3, c = (idx & 7) * 4;
            cpa16(&Bsn[buf][r][c], &g_WoT[(size_t)(n0 + r) * DM_ + k0 + c]);
        }
        cpa_commit();
    };

    issue(0, 0);

    for (int it = 0; it < DM_ / 32; it++) {
        const int buf = it & 1;
        cpa_wait0();
        __syncthreads();
        if (it + 1 < DM_ / 32) issue((it + 1) * 32, buf ^ 1);

        #pragma unroll
        for (int ks = 0; ks < 4; ks++) {
            uint32_t af[2][4];
            #pragma unroll
            for (int mt = 0; mt < 2; mt++) {
                int rr = warp * 32 + mt * 16 + g;
                af[mt][0] = As[buf][rr][ks*8 + tig];
                af[mt][1] = As[buf][rr + 8][ks*8 + tig];
                af[mt][2] = As[buf][rr][ks*8 + tig + 4];
                af[mt][3] = As[buf][rr + 8][ks*8 + tig + 4];
            }
            #pragma unroll
            for (int nt = 0; nt < 8; nt++) {
                uint32_t bf[2];
                bf[0] = Bsn[buf][nt*8 + g][ks*8 + tig];
                bf[1] = Bsn[buf][nt*8 + g][ks*8 + tig + 4];
                mma8(acc[0][nt], af[0], bf);
                mma8(acc[1][nt], af[1], bf);
            }
        }
    }

    #pragma unroll
    for (int mt = 0; mt < 2; mt++) {
        #pragma unroll
        for (int half = 0; half < 2; half++) {
            int m = m0 + warp * 32 + mt * 16 + g + half * 8;
            #pragma unroll
            for (int nt = 0; nt < 8; nt++) {
                int nn = nt * 8 + 2 * tig;
                float2 val = half ? make_float2(acc[mt][nt][2], acc[mt][nt][3])
                                  : make_float2(acc[mt][nt][0], acc[mt][nt][1]);
                *(float2*)&y[(size_t)m * DM_ + n0 + nn] = val;
            }
        }
    }
}

// ---------------------------------------------------------------------------
extern "C" void kernel_launch(void* const* d_in, const int* in_sizes, int n_in,
                              void* d_out, int out_size)
{
    const float* q  = (const float*)d_in[0];
    const float* k  = (const float*)d_in[1];
    const float* v  = (const float*)d_in[2];
    const float* Wq = (const float*)d_in[3];
    const float* Wk = (const float*)d_in[4];
    const float* Wv = (const float*)d_in[5];
    const float* Wo = (const float*)d_in[6];
    float* y = (float*)d_out;

    const int gemm_smem = (2*128*36 + 2*32*72) * (int)sizeof(uint32_t);   // 55296
    const int oproj_smem = (2*128*36 + 2*64*36) * (int)sizeof(uint32_t);  // 55296
    const int attn_smem = (128*68 + 64*68 + 64*72 + 128*68) * (int)sizeof(uint32_t); // 105472
    cudaFuncSetAttribute(qkv_proj_mma, cudaFuncAttributeMaxDynamicSharedMemorySize, gemm_smem);
    cudaFuncSetAttribute(attn_mma, cudaFuncAttributeMaxDynamicSharedMemorySize, attn_smem);
    cudaFuncSetAttribute(out_proj_mma, cudaFuncAttributeMaxDynamicSharedMemorySize, oproj_smem);

    cvt_inputs<<<dim3(NX_ / (256 * 4), 7), 256>>>(q, k, v, Wq, Wk, Wv, Wo);
    qkv_proj_mma<<<dim3(S_ * B_ / 128, H_, 3), 128, gemm_smem>>>();
    attn_mma<<<dim3(8, B_ * H_), 128, attn_smem>>>();
    out_proj_mma<<<dim3(S_ * B_ / 128, DM_ / 64), 128, oproj_smem>>>(y);
}